// round 9
// baseline (speedup 1.0000x reference)
#include <cuda_runtime.h>
#include <math.h>

#define FULL 0xFFFFFFFFu

constexpr int B  = 64;
constexpr int P  = 4096;
constexpr int W  = 16;
constexpr int D  = 128;
constexpr int Dw = 64;

// W1r: (D, D+4) row-major, stride 132.  W1t: (D, 2*Dw+2) row-major, stride 130.

__device__ float g_WT[D * D];     // transposed W1r_e: [k][d]
__device__ float g_bias[D];       // b1r + 0.95*W1r[:,130]
__device__ float g_src[W * D];
__device__ float g_tgt[W * D];
__device__ float g_emb[P * D];

// intra-launch gate (zero-init; reset by last consumer -> replay-safe)
__device__ int g_flagT, g_consT;

__device__ __forceinline__ void gate_wait(int* flag, int need) {
    if (threadIdx.x == 0) {
        while (atomicAdd(flag, 0) < need) __nanosleep(64);
    }
    __syncthreads();
    __threadfence();
}
__device__ __forceinline__ void gate_consume(int* flag, int* cons, int total) {
    if (threadIdx.x == 0) {
        if (atomicAdd(cons, 1) == total - 1) {
            atomicExch(cons, 0);
            atomicExch(flag, 0);
        }
    }
}
__device__ __forceinline__ void produce(int* flag) {
    __syncthreads();
    if (threadIdx.x == 0) {
        __threadfence();
        atomicAdd(flag, 1);
    }
}

// 4-way batched warp reduction (6 shuffles for 4 sums).
// lane group j = ((lane>>4)&1) | ((lane>>2)&2) holds total of s_j.
__device__ __forceinline__ float fold4(float s0, float s1, float s2, float s3) {
    bool hi16 = (threadIdx.x & 16) != 0;
    bool hi8  = (threadIdx.x & 8) != 0;
    float a   = hi16 ? s0 : s1;
    float v01 = (hi16 ? s1 : s0) + __shfl_xor_sync(FULL, a, 16);
    float b   = hi16 ? s2 : s3;
    float v23 = (hi16 ? s3 : s2) + __shfl_xor_sync(FULL, b, 16);
    float c   = hi8 ? v01 : v23;
    float vv  = (hi8 ? v23 : v01) + __shfl_xor_sync(FULL, c, 8);
    vv += __shfl_xor_sync(FULL, vv, 4);
    vv += __shfl_xor_sync(FULL, vv, 2);
    vv += __shfl_xor_sync(FULL, vv, 1);
    return vv;
}

// ---------------------------------------------------------------------------
// k_head (launch 1, 272 blocks x 256 thr):
//   [0,8)    transpose + bias -> flagT
//   [8,16)   src/tgt mini-GEMMs
//   [16,272) emb, 16 p each (8 warps x 2 p), gated on flagT
// ---------------------------------------------------------------------------
__global__ void __launch_bounds__(256, 6)
k_head(const float* __restrict__ part_emb,
       const float* __restrict__ wh_emb,
       const float* __restrict__ W1r,
       const float* __restrict__ b1r,
       const float* __restrict__ W1t,
       const float* __restrict__ b1t) {
    int bid = blockIdx.x, tid = threadIdx.x;

    if (bid < 8) {
        #pragma unroll
        for (int j = 0; j < 8; j++) {
            int e = bid * 2048 + tid + j * 256;
            int k = e >> 7, d = e & 127;
            g_WT[k * D + d] = W1r[d * 132 + k];
        }
        if (bid == 0 && tid < D)
            g_bias[tid] = b1r[tid] + 0.95f * W1r[tid * 132 + 130];
        produce(&g_flagT);
        return;
    }

    if (bid < 16) {
        #pragma unroll
        for (int r = 0; r < 2; r++) {
            int idx = (bid - 8) * 512 + r * 256 + tid;   // 0..4095
            int arr = idx >> 11;
            int rem = idx & 2047;
            int s = rem >> 7, d = rem & 127;
            const float* wrow = wh_emb + s * Dw;
            const float* wcol = W1t + d * 130 + arr * Dw;
            float acc = (arr == 0) ? b1t[d] : 0.f;
            #pragma unroll 8
            for (int k = 0; k < Dw; k++) acc = fmaf(wrow[k], wcol[k], acc);
            if (arr == 0) g_src[s * D + d] = acc;
            else          g_tgt[s * D + d] = acc;
        }
        return;
    }

    // ---- emb role: 8 warps x 2 p ----
    gate_wait(&g_flagT, 8);
    gate_consume(&g_flagT, &g_consT, 256);

    int w = tid >> 5, lane = tid & 31;
    int p0 = ((bid - 16) * 8 + w) * 2;
    const float4* e0 = (const float4*)(part_emb + p0 * D);
    const float4* e1 = e0 + (D / 4);
    float4 bias = ((const float4*)g_bias)[lane];
    float4 a0 = bias, a1 = bias;
    #pragma unroll 4
    for (int k4 = 0; k4 < 32; k4++) {
        const float4* wt = (const float4*)(g_WT + k4 * 4 * D);
        float4 w0 = __ldg(&wt[lane]);
        float4 w1 = __ldg(&wt[32 + lane]);
        float4 w2 = __ldg(&wt[64 + lane]);
        float4 w3 = __ldg(&wt[96 + lane]);
        float4 ea = __ldg(&e0[k4]);
        float4 eb = __ldg(&e1[k4]);
        #define ACC(A, E) \
            A.x = fmaf(E.x, w0.x, fmaf(E.y, w1.x, fmaf(E.z, w2.x, fmaf(E.w, w3.x, A.x)))); \
            A.y = fmaf(E.x, w0.y, fmaf(E.y, w1.y, fmaf(E.z, w2.y, fmaf(E.w, w3.y, A.y)))); \
            A.z = fmaf(E.x, w0.z, fmaf(E.y, w1.z, fmaf(E.z, w2.z, fmaf(E.w, w3.z, A.z)))); \
            A.w = fmaf(E.x, w0.w, fmaf(E.y, w1.w, fmaf(E.z, w2.w, fmaf(E.w, w3.w, A.w))));
        ACC(a0, ea) ACC(a1, eb)
        #undef ACC
    }
    ((float4*)(g_emb + (p0 + 0) * D))[lane] = a0;
    ((float4*)(g_emb + (p0 + 1) * D))[lane] = a1;
}

// ---------------------------------------------------------------------------
// k_main (launch 2, 1536 blocks x 256 thr, 6 blocks/SM):
//   [0,1024)    transfer, 4 p each (8 warps = 4 p x 2 parity)
//   [1024,1536) reorder, 8 p each (warp per p)
// ---------------------------------------------------------------------------
__global__ void __launch_bounds__(256, 6)
k_main(const float* __restrict__ cur_stock,
       const float* __restrict__ demand,
       const float* __restrict__ lead,
       const float* __restrict__ wstk,
       const float* __restrict__ wdem,
       const float* __restrict__ W1r,
       const float* __restrict__ W2r,
       const float* __restrict__ b2r,
       const float* __restrict__ W1t,
       const float* __restrict__ W2t,
       const float* __restrict__ b2t,
       float* __restrict__ outR,
       float* __restrict__ outT) {
    __shared__ union {
        struct {
            float sSrc[W * D];
            float sTgt[W * D];
            float sWs[D], sWd[D], sV[D];
            float sRes[256 * 5];
            float sSv[4 * 17];
            int   sPl[4 * 17];
            int   sTl[4 * 17];
        } t;
        struct {
            float sC[4 * 128];
            float sX[8][65];
        } r;
    } sm;

    int tid = threadIdx.x;
    int bid = blockIdx.x;
    int w = tid >> 5, lane = tid & 31;
    int jm = ((lane >> 4) & 1) | ((lane >> 2) & 2);

    if (bid >= 1024) {
        // ================= reorder role =================
        if (tid < 128) {
            sm.r.sC[tid]       = W1r[tid * 132 + 128];
            sm.r.sC[128 + tid] = W1r[tid * 132 + 129];
            sm.r.sC[256 + tid] = W1r[tid * 132 + 131];
            sm.r.sC[384 + tid] = W2r[tid];
        }
        __syncthreads();

        float4 c0 = ((float4*)sm.r.sC)[lane];
        float4 c1 = ((float4*)(sm.r.sC + 128))[lane];
        float4 c3 = ((float4*)(sm.r.sC + 256))[lane];
        float4 v  = ((float4*)(sm.r.sC + 384))[lane];

        int pbase = (bid - 1024) * 8;
        int p = pbase + w;
        float4 e = ((const float4*)(g_emb + p * D))[lane];

        #pragma unroll 2
        for (int bq = 0; bq < B; bq += 8) {
            float sA[8];
            #pragma unroll
            for (int j = 0; j < 8; j++) {
                int item = (bq + j) * P + p;
                float df = __ldg(&demand[item]);
                float lt = __ldg(&lead[item]);
                float cs = __ldg(&cur_stock[item]);
                float4 h;
                h.x = fmaxf(fmaf(cs, c3.x, fmaf(lt, c1.x, fmaf(df, c0.x, e.x))), 0.f);
                h.y = fmaxf(fmaf(cs, c3.y, fmaf(lt, c1.y, fmaf(df, c0.y, e.y))), 0.f);
                h.z = fmaxf(fmaf(cs, c3.z, fmaf(lt, c1.z, fmaf(df, c0.z, e.z))), 0.f);
                h.w = fmaxf(fmaf(cs, c3.w, fmaf(lt, c1.w, fmaf(df, c0.w, e.w))), 0.f);
                sA[j] = fmaf(h.x, v.x, fmaf(h.y, v.y, fmaf(h.z, v.z, h.w * v.w)));
            }
            float t0 = fold4(sA[0], sA[1], sA[2], sA[3]);
            float t1 = fold4(sA[4], sA[5], sA[6], sA[7]);
            if ((lane & 7) == 0) {
                sm.r.sX[w][bq + jm]     = t0;
                sm.r.sX[w][bq + 4 + jm] = t1;
            }
        }
        __syncthreads();

        float bb = b2r[0];
        for (int i = tid; i < 512; i += 256) {
            int b = i >> 3, pw = i & 7;
            float x = sm.r.sX[pw][b] + bb;
            outR[b * P + pbase + pw] = fmaxf(x, 0.f) + log1pf(__expf(-fabsf(x)));
        }
        return;
    }

    // ================= transfer role: 4 p x 2 parity warps =================
    {
        const float4* gs = (const float4*)g_src;
        const float4* gt = (const float4*)g_tgt;
        float4* ss = (float4*)sm.t.sSrc;
        float4* st4 = (float4*)sm.t.sTgt;
        for (int i = tid; i < W * D / 4; i += 256) { ss[i] = gs[i]; st4[i] = gt[i]; }
    }
    if (tid < D) {
        sm.t.sWs[tid] = W1t[tid * 130 + 128];
        sm.t.sWd[tid] = W1t[tid * 130 + 129];
        sm.t.sV[tid]  = W2t[tid];
    }

    int pslot = w >> 1;
    int q = w & 1;
    int pbase = bid * 4;
    int p = pbase + pslot;

    float sv = 0.f;
    if (lane < W) sv = wstk[lane * P + p] - wdem[lane * P + p];
    unsigned pos = __ballot_sync(FULL, (lane < W) && (sv > 0.f));
    unsigned neg = __ballot_sync(FULL, (lane < W) && (sv < 0.f));
    int npos = __popc(pos);
    int nneg = __popc(neg);

    if (q == 0 && lane < W) {
        sm.t.sSv[pslot * 17 + lane] = sv;
        unsigned bit = 1u << lane;
        if (pos & bit) sm.t.sPl[pslot * 17 + __popc(pos & (bit - 1))] = lane;
        if (neg & bit) sm.t.sTl[pslot * 17 + __popc(neg & (bit - 1))] = lane;
    }
    __syncthreads();

    float4 ws4 = ((float4*)sm.t.sWs)[lane];
    float4 wd4 = ((float4*)sm.t.sWd)[lane];
    float4 v4  = ((float4*)sm.t.sV)[lane];

    const float* svRow = sm.t.sSv + pslot * 17;
    const int*   tl    = sm.t.sTl + pslot * 17;

    for (int si = q; si < npos; si += 2) {
        int s = sm.t.sPl[pslot * 17 + si];
        float ssp = svRow[s];
        float4 sr = ((float4*)(sm.t.sSrc + s * D))[lane];
        float4 base;
        base.x = fmaf(ssp, ws4.x, sr.x);
        base.y = fmaf(ssp, ws4.y, sr.y);
        base.z = fmaf(ssp, ws4.z, sr.z);
        base.w = fmaf(ssp, ws4.w, sr.w);
        for (int ti = 0; ti < nneg; ti += 8) {
            float sA[8];
            int tt[8];
            #pragma unroll
            for (int j = 0; j < 8; j++) {
                int idx = ti + j; if (idx > nneg - 1) idx = nneg - 1;
                int t = tl[idx];
                tt[j] = t;
                float dn = -svRow[t];
                float4 tg = ((float4*)(sm.t.sTgt + t * D))[lane];
                float4 h;
                h.x = fmaxf(base.x + fmaf(dn, wd4.x, tg.x), 0.f);
                h.y = fmaxf(base.y + fmaf(dn, wd4.y, tg.y), 0.f);
                h.z = fmaxf(base.z + fmaf(dn, wd4.z, tg.z), 0.f);
                h.w = fmaxf(base.w + fmaf(dn, wd4.w, tg.w), 0.f);
                sA[j] = fmaf(h.x, v4.x, fmaf(h.y, v4.y, fmaf(h.z, v4.z, h.w * v4.w)));
            }
            float tot0 = fold4(sA[0], sA[1], sA[2], sA[3]);
            float tot1 = fold4(sA[4], sA[5], sA[6], sA[7]);
            int tm0 = (lane & 16) ? ((lane & 8) ? tt[3] : tt[1])
                                  : ((lane & 8) ? tt[2] : tt[0]);
            int tm1 = (lane & 16) ? ((lane & 8) ? tt[7] : tt[5])
                                  : ((lane & 8) ? tt[6] : tt[4]);
            if (((lane & 7) == 0) && (ti + jm < nneg))
                sm.t.sRes[(s * 16 + tm0) * 5 + pslot] = tot0;
            if (((lane & 7) == 0) && (ti + 4 + jm < nneg))
                sm.t.sRes[(s * 16 + tm1) * 5 + pslot] = tot1;
        }
    }
    __syncthreads();

    float b2 = b2t[0];
    for (int i = tid; i < 1024; i += 256) {
        int st = i >> 2, pw = i & 3;
        int s = st >> 4, t = st & 15;
        float svs = sm.t.sSv[pw * 17 + s];
        float svt = sm.t.sSv[pw * 17 + t];
        float val = 0.f;
        if (svs > 0.f && svt < 0.f) {
            float x = sm.t.sRes[st * 5 + pw] + b2;
            val = fminf(svs, -svt) * __fdividef(1.f, 1.f + __expf(-x));
        }
        outT[st * P + pbase + pw] = val;
    }
}

// ---------------------------------------------------------------------------
extern "C" void kernel_launch(void* const* d_in, const int* in_sizes, int n_in,
                              void* d_out, int out_size) {
    const float* current_stock     = (const float*)d_in[0];
    const float* demand_forecast   = (const float*)d_in[1];
    const float* lead_times        = (const float*)d_in[2];
    const float* warehouse_stocks  = (const float*)d_in[3];
    const float* warehouse_demands = (const float*)d_in[4];
    const float* part_emb          = (const float*)d_in[5];
    const float* wh_emb            = (const float*)d_in[6];
    const float* W1r               = (const float*)d_in[7];
    const float* b1r               = (const float*)d_in[8];
    const float* W2r               = (const float*)d_in[9];
    const float* b2r               = (const float*)d_in[10];
    const float* W1t               = (const float*)d_in[11];
    const float* b1t               = (const float*)d_in[12];
    const float* W2t               = (const float*)d_in[13];
    const float* b2t               = (const float*)d_in[14];

    float* out_reorder  = (float*)d_out;              // [B, P]
    float* out_transfer = (float*)d_out + B * P;      // [W, W, P]

    k_head<<<272, 256>>>(part_emb, wh_emb, W1r, b1r, W1t, b1t);
    k_main<<<1536, 256>>>(current_stock, demand_forecast, lead_times,
                          warehouse_stocks, warehouse_demands,
                          W1r, W2r, b2r, W1t, W2t, b2t,
                          out_reorder, out_transfer);
}

// round 10
// speedup vs baseline: 1.0581x; 1.0581x over previous
#include <cuda_runtime.h>
#include <math.h>

#define FULL 0xFFFFFFFFu

constexpr int B  = 64;
constexpr int P  = 4096;
constexpr int W  = 16;
constexpr int D  = 128;
constexpr int Dw = 64;

// W1r: (D, D+4) row-major, stride 132.  W1t: (D, 2*Dw+2) row-major, stride 130.

__device__ float g_WT[D * D];     // transposed W1r_e: [k][d]
__device__ float g_bias[D];       // b1r + 0.95*W1r[:,130]
__device__ float g_src[W * D];
__device__ float g_tgt[W * D];
__device__ float g_emb[P * D];

// intra-launch gate (zero-init; reset by last consumer -> replay-safe)
__device__ int g_flagT, g_consT;

__device__ __forceinline__ void gate_wait(int* flag, int need) {
    if (threadIdx.x == 0) {
        while (atomicAdd(flag, 0) < need) __nanosleep(64);
    }
    __syncthreads();
    __threadfence();
}
__device__ __forceinline__ void gate_consume(int* flag, int* cons, int total) {
    if (threadIdx.x == 0) {
        if (atomicAdd(cons, 1) == total - 1) {
            atomicExch(cons, 0);
            atomicExch(flag, 0);
        }
    }
}
__device__ __forceinline__ void produce(int* flag) {
    __syncthreads();
    if (threadIdx.x == 0) {
        __threadfence();
        atomicAdd(flag, 1);
    }
}

// 4-way batched warp reduction (6 shuffles for 4 sums).
// lane group j = ((lane>>4)&1) | ((lane>>2)&2) holds total of s_j.
__device__ __forceinline__ float fold4(float s0, float s1, float s2, float s3) {
    bool hi16 = (threadIdx.x & 16) != 0;
    bool hi8  = (threadIdx.x & 8) != 0;
    float a   = hi16 ? s0 : s1;
    float v01 = (hi16 ? s1 : s0) + __shfl_xor_sync(FULL, a, 16);
    float b   = hi16 ? s2 : s3;
    float v23 = (hi16 ? s3 : s2) + __shfl_xor_sync(FULL, b, 16);
    float c   = hi8 ? v01 : v23;
    float vv  = (hi8 ? v23 : v01) + __shfl_xor_sync(FULL, c, 8);
    vv += __shfl_xor_sync(FULL, vv, 4);
    vv += __shfl_xor_sync(FULL, vv, 2);
    vv += __shfl_xor_sync(FULL, vv, 1);
    return vv;
}

// ---------------------------------------------------------------------------
// k_head (launch 1, 272 blocks x 256 thr):
//   [0,8)    transpose + bias -> flagT
//   [8,16)   src/tgt mini-GEMMs
//   [16,272) emb, 16 p each (8 warps x 2 p), gated on flagT
// ---------------------------------------------------------------------------
__global__ void k_head(const float* __restrict__ part_emb,
                       const float* __restrict__ wh_emb,
                       const float* __restrict__ W1r,
                       const float* __restrict__ b1r,
                       const float* __restrict__ W1t,
                       const float* __restrict__ b1t) {
    int bid = blockIdx.x, tid = threadIdx.x;

    if (bid < 8) {
        #pragma unroll
        for (int j = 0; j < 8; j++) {
            int e = bid * 2048 + tid + j * 256;
            int k = e >> 7, d = e & 127;
            g_WT[k * D + d] = W1r[d * 132 + k];
        }
        if (bid == 0 && tid < D)
            g_bias[tid] = b1r[tid] + 0.95f * W1r[tid * 132 + 130];
        produce(&g_flagT);
        return;
    }

    if (bid < 16) {
        #pragma unroll
        for (int r = 0; r < 2; r++) {
            int idx = (bid - 8) * 512 + r * 256 + tid;   // 0..4095
            int arr = idx >> 11;
            int rem = idx & 2047;
            int s = rem >> 7, d = rem & 127;
            const float* wrow = wh_emb + s * Dw;
            const float* wcol = W1t + d * 130 + arr * Dw;
            float acc = (arr == 0) ? b1t[d] : 0.f;
            #pragma unroll 8
            for (int k = 0; k < Dw; k++) acc = fmaf(wrow[k], wcol[k], acc);
            if (arr == 0) g_src[s * D + d] = acc;
            else          g_tgt[s * D + d] = acc;
        }
        return;
    }

    // ---- emb role: 8 warps x 2 p ----
    gate_wait(&g_flagT, 8);
    gate_consume(&g_flagT, &g_consT, 256);

    int w = tid >> 5, lane = tid & 31;
    int p0 = ((bid - 16) * 8 + w) * 2;
    const float4* e0 = (const float4*)(part_emb + p0 * D);
    const float4* e1 = e0 + (D / 4);
    float4 bias = ((const float4*)g_bias)[lane];
    float4 a0 = bias, a1 = bias;
    #pragma unroll 4
    for (int k4 = 0; k4 < 32; k4++) {
        const float4* wt = (const float4*)(g_WT + k4 * 4 * D);
        float4 w0 = __ldg(&wt[lane]);
        float4 w1 = __ldg(&wt[32 + lane]);
        float4 w2 = __ldg(&wt[64 + lane]);
        float4 w3 = __ldg(&wt[96 + lane]);
        float4 ea = __ldg(&e0[k4]);
        float4 eb = __ldg(&e1[k4]);
        #define ACC(A, E) \
            A.x = fmaf(E.x, w0.x, fmaf(E.y, w1.x, fmaf(E.z, w2.x, fmaf(E.w, w3.x, A.x)))); \
            A.y = fmaf(E.x, w0.y, fmaf(E.y, w1.y, fmaf(E.z, w2.y, fmaf(E.w, w3.y, A.y)))); \
            A.z = fmaf(E.x, w0.z, fmaf(E.y, w1.z, fmaf(E.z, w2.z, fmaf(E.w, w3.z, A.z)))); \
            A.w = fmaf(E.x, w0.w, fmaf(E.y, w1.w, fmaf(E.z, w2.w, fmaf(E.w, w3.w, A.w))));
        ACC(a0, ea) ACC(a1, eb)
        #undef ACC
    }
    ((float4*)(g_emb + (p0 + 0) * D))[lane] = a0;
    ((float4*)(g_emb + (p0 + 1) * D))[lane] = a1;
}

// ---------------------------------------------------------------------------
// k_main (launch 2, 1536 blocks x 256 thr, 5 blocks/SM — the R7 sweet spot):
//   [0,1024)    transfer, 4 p each (8 warps = 4 p x 2 parity)
//   [1024,1536) reorder, 8 p each (warp per p)
// ---------------------------------------------------------------------------
__global__ void __launch_bounds__(256, 5)
k_main(const float* __restrict__ cur_stock,
       const float* __restrict__ demand,
       const float* __restrict__ lead,
       const float* __restrict__ wstk,
       const float* __restrict__ wdem,
       const float* __restrict__ W1r,
       const float* __restrict__ W2r,
       const float* __restrict__ b2r,
       const float* __restrict__ W1t,
       const float* __restrict__ W2t,
       const float* __restrict__ b2t,
       float* __restrict__ outR,
       float* __restrict__ outT) {
    __shared__ union {
        struct {
            float sSrc[W * D];
            float sTgt[W * D];
            float sWs[D], sWd[D], sV[D];
            float sRes[256 * 5];
            float sSv[4 * 17];
            int   sPl[4 * 17];
            int   sTl[4 * 17];
        } t;
        struct {
            float sC[4 * 128];
            float sX[8][65];
        } r;
    } sm;

    int tid = threadIdx.x;
    int bid = blockIdx.x;
    int w = tid >> 5, lane = tid & 31;
    int jm = ((lane >> 4) & 1) | ((lane >> 2) & 2);

    if (bid >= 1024) {
        // ================= reorder role =================
        if (tid < 128) {
            sm.r.sC[tid]       = W1r[tid * 132 + 128];
            sm.r.sC[128 + tid] = W1r[tid * 132 + 129];
            sm.r.sC[256 + tid] = W1r[tid * 132 + 131];
            sm.r.sC[384 + tid] = W2r[tid];
        }
        __syncthreads();

        float4 c0 = ((float4*)sm.r.sC)[lane];
        float4 c1 = ((float4*)(sm.r.sC + 128))[lane];
        float4 c3 = ((float4*)(sm.r.sC + 256))[lane];
        float4 v  = ((float4*)(sm.r.sC + 384))[lane];

        int pbase = (bid - 1024) * 8;
        int p = pbase + w;
        float4 e = ((const float4*)(g_emb + p * D))[lane];

        #pragma unroll 2
        for (int bq = 0; bq < B; bq += 8) {
            float sA[8];
            #pragma unroll
            for (int j = 0; j < 8; j++) {
                int item = (bq + j) * P + p;
                float df = __ldg(&demand[item]);
                float lt = __ldg(&lead[item]);
                float cs = __ldg(&cur_stock[item]);
                float4 h;
                h.x = fmaxf(fmaf(cs, c3.x, fmaf(lt, c1.x, fmaf(df, c0.x, e.x))), 0.f);
                h.y = fmaxf(fmaf(cs, c3.y, fmaf(lt, c1.y, fmaf(df, c0.y, e.y))), 0.f);
                h.z = fmaxf(fmaf(cs, c3.z, fmaf(lt, c1.z, fmaf(df, c0.z, e.z))), 0.f);
                h.w = fmaxf(fmaf(cs, c3.w, fmaf(lt, c1.w, fmaf(df, c0.w, e.w))), 0.f);
                sA[j] = fmaf(h.x, v.x, fmaf(h.y, v.y, fmaf(h.z, v.z, h.w * v.w)));
            }
            float t0 = fold4(sA[0], sA[1], sA[2], sA[3]);
            float t1 = fold4(sA[4], sA[5], sA[6], sA[7]);
            if ((lane & 7) == 0) {
                sm.r.sX[w][bq + jm]     = t0;
                sm.r.sX[w][bq + 4 + jm] = t1;
            }
        }
        __syncthreads();

        float bb = b2r[0];
        for (int i = tid; i < 512; i += 256) {
            int b = i >> 3, pw = i & 7;
            float x = sm.r.sX[pw][b] + bb;
            outR[b * P + pbase + pw] = fmaxf(x, 0.f) + log1pf(__expf(-fabsf(x)));
        }
        return;
    }

    // ================= transfer role: 4 p x 2 parity warps =================
    {
        const float4* gs = (const float4*)g_src;
        const float4* gt = (const float4*)g_tgt;
        float4* ss = (float4*)sm.t.sSrc;
        float4* st4 = (float4*)sm.t.sTgt;
        for (int i = tid; i < W * D / 4; i += 256) { ss[i] = gs[i]; st4[i] = gt[i]; }
    }
    if (tid < D) {
        sm.t.sWs[tid] = W1t[tid * 130 + 128];
        sm.t.sWd[tid] = W1t[tid * 130 + 129];
        sm.t.sV[tid]  = W2t[tid];
    }

    int pslot = w >> 1;
    int q = w & 1;
    int pbase = bid * 4;
    int p = pbase + pslot;

    float sv = 0.f;
    if (lane < W) sv = wstk[lane * P + p] - wdem[lane * P + p];
    unsigned pos = __ballot_sync(FULL, (lane < W) && (sv > 0.f));
    unsigned neg = __ballot_sync(FULL, (lane < W) && (sv < 0.f));
    int npos = __popc(pos);
    int nneg = __popc(neg);

    if (q == 0 && lane < W) {
        sm.t.sSv[pslot * 17 + lane] = sv;
        unsigned bit = 1u << lane;
        if (pos & bit) sm.t.sPl[pslot * 17 + __popc(pos & (bit - 1))] = lane;
        if (neg & bit) sm.t.sTl[pslot * 17 + __popc(neg & (bit - 1))] = lane;
    }
    __syncthreads();

    float4 ws4 = ((float4*)sm.t.sWs)[lane];
    float4 wd4 = ((float4*)sm.t.sWd)[lane];
    float4 v4  = ((float4*)sm.t.sV)[lane];

    const float* svRow = sm.t.sSv + pslot * 17;
    const int*   tl    = sm.t.sTl + pslot * 17;

    for (int si = q; si < npos; si += 2) {
        int s = sm.t.sPl[pslot * 17 + si];
        float ssp = svRow[s];
        float4 sr = ((float4*)(sm.t.sSrc + s * D))[lane];
        float4 base;
        base.x = fmaf(ssp, ws4.x, sr.x);
        base.y = fmaf(ssp, ws4.y, sr.y);
        base.z = fmaf(ssp, ws4.z, sr.z);
        base.w = fmaf(ssp, ws4.w, sr.w);
        for (int ti = 0; ti < nneg; ti += 8) {
            float sA[8];
            int tt[8];
            #pragma unroll
            for (int j = 0; j < 8; j++) {
                int idx = ti + j; if (idx > nneg - 1) idx = nneg - 1;
                int t = tl[idx];
                tt[j] = t;
                float dn = -svRow[t];
                float4 tg = ((float4*)(sm.t.sTgt + t * D))[lane];
                float4 h;
                h.x = fmaxf(base.x + fmaf(dn, wd4.x, tg.x), 0.f);
                h.y = fmaxf(base.y + fmaf(dn, wd4.y, tg.y), 0.f);
                h.z = fmaxf(base.z + fmaf(dn, wd4.z, tg.z), 0.f);
                h.w = fmaxf(base.w + fmaf(dn, wd4.w, tg.w), 0.f);
                sA[j] = fmaf(h.x, v4.x, fmaf(h.y, v4.y, fmaf(h.z, v4.z, h.w * v4.w)));
            }
            float tot0 = fold4(sA[0], sA[1], sA[2], sA[3]);
            float tot1 = fold4(sA[4], sA[5], sA[6], sA[7]);
            int tm0 = (lane & 16) ? ((lane & 8) ? tt[3] : tt[1])
                                  : ((lane & 8) ? tt[2] : tt[0]);
            int tm1 = (lane & 16) ? ((lane & 8) ? tt[7] : tt[5])
                                  : ((lane & 8) ? tt[6] : tt[4]);
            if (((lane & 7) == 0) && (ti + jm < nneg))
                sm.t.sRes[(s * 16 + tm0) * 5 + pslot] = tot0;
            if (((lane & 7) == 0) && (ti + 4 + jm < nneg))
                sm.t.sRes[(s * 16 + tm1) * 5 + pslot] = tot1;
        }
    }
    __syncthreads();

    float b2 = b2t[0];
    for (int i = tid; i < 1024; i += 256) {
        int st = i >> 2, pw = i & 3;
        int s = st >> 4, t = st & 15;
        float svs = sm.t.sSv[pw * 17 + s];
        float svt = sm.t.sSv[pw * 17 + t];
        float val = 0.f;
        if (svs > 0.f && svt < 0.f) {
            float x = sm.t.sRes[st * 5 + pw] + b2;
            val = fminf(svs, -svt) * __fdividef(1.f, 1.f + __expf(-x));
        }
        outT[st * P + pbase + pw] = val;
    }
}

// ---------------------------------------------------------------------------
extern "C" void kernel_launch(void* const* d_in, const int* in_sizes, int n_in,
                              void* d_out, int out_size) {
    const float* current_stock     = (const float*)d_in[0];
    const float* demand_forecast   = (const float*)d_in[1];
    const float* lead_times        = (const float*)d_in[2];
    const float* warehouse_stocks  = (const float*)d_in[3];
    const float* warehouse_demands = (const float*)d_in[4];
    const float* part_emb          = (const float*)d_in[5];
    const float* wh_emb            = (const float*)d_in[6];
    const float* W1r               = (const float*)d_in[7];
    const float* b1r               = (const float*)d_in[8];
    const float* W2r               = (const float*)d_in[9];
    const float* b2r               = (const float*)d_in[10];
    const float* W1t               = (const float*)d_in[11];
    const float* b1t               = (const float*)d_in[12];
    const float* W2t               = (const float*)d_in[13];
    const float* b2t               = (const float*)d_in[14];

    float* out_reorder  = (float*)d_out;              // [B, P]
    float* out_transfer = (float*)d_out + B * P;      // [W, W, P]

    k_head<<<272, 256>>>(part_emb, wh_emb, W1r, b1r, W1t, b1t);
    k_main<<<1536, 256>>>(current_stock, demand_forecast, lead_times,
                          warehouse_stocks, warehouse_demands,
                          W1r, W2r, b2r, W1t, W2t, b2t,
                          out_reorder, out_transfer);
}

// round 11
// speedup vs baseline: 1.2010x; 1.1350x over previous
#include <cuda_runtime.h>
#include <math.h>

#define FULL 0xFFFFFFFFu

constexpr int B  = 64;
constexpr int P  = 4096;
constexpr int W  = 16;
constexpr int D  = 128;
constexpr int Dw = 64;

// W1r: (D, D+4) row-major, stride 132.  W1t: (D, 2*Dw+2) row-major, stride 130.

__device__ float g_src[W * D];
__device__ float g_tgt[W * D];
__device__ float g_emb[P * D];

// intra-launch gates (zero-init; reset by last consumer -> replay-safe)
__device__ int g_flagS, g_consS;
__device__ int g_flagE, g_consE;

__device__ __forceinline__ void gate_wait(int* flag, int need) {
    if (threadIdx.x == 0) {
        while (atomicAdd(flag, 0) < need) __nanosleep(64);
    }
    __syncthreads();
    __threadfence();
}
__device__ __forceinline__ void gate_consume(int* flag, int* cons, int total) {
    if (threadIdx.x == 0) {
        if (atomicAdd(cons, 1) == total - 1) {
            atomicExch(cons, 0);
            atomicExch(flag, 0);
        }
    }
}
__device__ __forceinline__ void produce(int* flag) {
    __syncthreads();
    if (threadIdx.x == 0) {
        __threadfence();
        atomicAdd(flag, 1);
    }
}

// 4-way batched warp reduction (6 shuffles for 4 sums).
// lane group j = ((lane>>4)&1) | ((lane>>2)&2) holds total of s_j.
__device__ __forceinline__ float fold4(float s0, float s1, float s2, float s3) {
    bool hi16 = (threadIdx.x & 16) != 0;
    bool hi8  = (threadIdx.x & 8) != 0;
    float a   = hi16 ? s0 : s1;
    float v01 = (hi16 ? s1 : s0) + __shfl_xor_sync(FULL, a, 16);
    float b   = hi16 ? s2 : s3;
    float v23 = (hi16 ? s3 : s2) + __shfl_xor_sync(FULL, b, 16);
    float c   = hi8 ? v01 : v23;
    float vv  = (hi8 ? v23 : v01) + __shfl_xor_sync(FULL, c, 8);
    vv += __shfl_xor_sync(FULL, vv, 4);
    vv += __shfl_xor_sync(FULL, vv, 2);
    vv += __shfl_xor_sync(FULL, vv, 1);
    return vv;
}

// ---------------------------------------------------------------------------
// k_all: single launch, 1800 blocks x 256 thr, 5 blocks/SM
//   [0,8)       src/tgt mini-GEMMs                 -> flagS
//   [8,264)     emb, 16 p each, smem-tiled 2-pass  -> flagE (256 total)
//   [264,1288)  transfer, 4 p each                  : wait flagS
//   [1288,1800) reorder, 8 p each                   : wait flagE==256
// ---------------------------------------------------------------------------
__global__ void __launch_bounds__(256, 5)
k_all(const float* __restrict__ cur_stock,
      const float* __restrict__ demand,
      const float* __restrict__ lead,
      const float* __restrict__ wstk,
      const float* __restrict__ wdem,
      const float* __restrict__ part_emb,
      const float* __restrict__ wh_emb,
      const float* __restrict__ W1r,
      const float* __restrict__ b1r,
      const float* __restrict__ W2r,
      const float* __restrict__ b2r,
      const float* __restrict__ W1t,
      const float* __restrict__ b1t,
      const float* __restrict__ W2t,
      const float* __restrict__ b2t,
      float* __restrict__ outR,
      float* __restrict__ outT) {
    __shared__ union {
        struct {
            float sSrc[W * D];
            float sTgt[W * D];
            float sWs[D], sWd[D], sV[D];
            float sRes[256 * 5];
            float sSv[4 * 17];
            int   sPl[4 * 17];
            int   sTl[4 * 17];
        } t;
        struct {
            float sC[4 * 128];
            float sX[8][65];
        } r;
        struct {
            float sWT[64 * 132];    // half-k weight tile, transposed [k][d]
            float sBias[128];
        } e;
    } sm;

    int tid = threadIdx.x;
    int bid = blockIdx.x;
    int w = tid >> 5, lane = tid & 31;
    int jm = ((lane >> 4) & 1) | ((lane >> 2) & 2);

    if (bid < 8) {
        // ---------- src/tgt role: 2 dots per thread ----------
        #pragma unroll
        for (int r = 0; r < 2; r++) {
            int idx = bid * 512 + r * 256 + tid;   // 0..4095
            int arr = idx >> 11;
            int rem = idx & 2047;
            int s = rem >> 7, d = rem & 127;
            const float* wrow = wh_emb + s * Dw;
            const float* wcol = W1t + d * 130 + arr * Dw;
            float acc = (arr == 0) ? b1t[d] : 0.f;
            #pragma unroll 8
            for (int k = 0; k < Dw; k++) acc = fmaf(wrow[k], wcol[k], acc);
            if (arr == 0) g_src[s * D + d] = acc;
            else          g_tgt[s * D + d] = acc;
        }
        produce(&g_flagS);
        return;
    }

    if (bid < 264) {
        // ---------- emb role: 8 warps x 2 p, 2-pass k-split smem tile ----------
        int p0 = ((bid - 8) * 8 + w) * 2;
        float4 a0, a1;
        #pragma unroll
        for (int pass = 0; pass < 2; pass++) {
            // coalesced transposing tile load: W1r[d][pass*64+k] -> sWT[k*132+d]
            for (int i = tid; i < 8192; i += 256) {
                int d = i >> 6, k = i & 63;
                sm.e.sWT[k * 132 + d] = W1r[d * 132 + pass * 64 + k];
            }
            if (pass == 0 && tid < 128)
                sm.e.sBias[tid] = b1r[tid] + 0.95f * W1r[tid * 132 + 130];
            __syncthreads();
            if (pass == 0) {
                float4 bias = ((const float4*)sm.e.sBias)[lane];
                a0 = bias; a1 = bias;
            }
            const float4* e0 = (const float4*)(part_emb + p0 * D) + pass * 16;
            const float4* e1 = (const float4*)(part_emb + (p0 + 1) * D) + pass * 16;
            #pragma unroll 4
            for (int k4 = 0; k4 < 16; k4++) {
                const float* wt = sm.e.sWT + k4 * 4 * 132;
                float4 w0 = ((const float4*)(wt))[lane];
                float4 w1 = ((const float4*)(wt + 132))[lane];
                float4 w2 = ((const float4*)(wt + 264))[lane];
                float4 w3 = ((const float4*)(wt + 396))[lane];
                float4 ea = __ldg(&e0[k4]);
                float4 eb = __ldg(&e1[k4]);
                #define ACC(A, E) \
                    A.x = fmaf(E.x, w0.x, fmaf(E.y, w1.x, fmaf(E.z, w2.x, fmaf(E.w, w3.x, A.x)))); \
                    A.y = fmaf(E.x, w0.y, fmaf(E.y, w1.y, fmaf(E.z, w2.y, fmaf(E.w, w3.y, A.y)))); \
                    A.z = fmaf(E.x, w0.z, fmaf(E.y, w1.z, fmaf(E.z, w2.z, fmaf(E.w, w3.z, A.z)))); \
                    A.w = fmaf(E.x, w0.w, fmaf(E.y, w1.w, fmaf(E.z, w2.w, fmaf(E.w, w3.w, A.w))));
                ACC(a0, ea) ACC(a1, eb)
                #undef ACC
            }
            __syncthreads();    // tile reuse barrier
        }
        ((float4*)(g_emb + (p0 + 0) * D))[lane] = a0;
        ((float4*)(g_emb + (p0 + 1) * D))[lane] = a1;
        produce(&g_flagE);
        return;
    }

    if (bid < 1288) {
        // ================= transfer role: 4 p x 2 parity warps =================
        gate_wait(&g_flagS, 8);
        gate_consume(&g_flagS, &g_consS, 1024);

        {
            const float4* gs = (const float4*)g_src;
            const float4* gt = (const float4*)g_tgt;
            float4* ss = (float4*)sm.t.sSrc;
            float4* st4 = (float4*)sm.t.sTgt;
            for (int i = tid; i < W * D / 4; i += 256) { ss[i] = gs[i]; st4[i] = gt[i]; }
        }
        if (tid < D) {
            sm.t.sWs[tid] = W1t[tid * 130 + 128];
            sm.t.sWd[tid] = W1t[tid * 130 + 129];
            sm.t.sV[tid]  = W2t[tid];
        }

        int pslot = w >> 1;
        int q = w & 1;
        int pbase = (bid - 264) * 4;
        int p = pbase + pslot;

        float sv = 0.f;
        if (lane < W) sv = wstk[lane * P + p] - wdem[lane * P + p];
        unsigned pos = __ballot_sync(FULL, (lane < W) && (sv > 0.f));
        unsigned neg = __ballot_sync(FULL, (lane < W) && (sv < 0.f));
        int npos = __popc(pos);
        int nneg = __popc(neg);

        if (q == 0 && lane < W) {
            sm.t.sSv[pslot * 17 + lane] = sv;
            unsigned bit = 1u << lane;
            if (pos & bit) sm.t.sPl[pslot * 17 + __popc(pos & (bit - 1))] = lane;
            if (neg & bit) sm.t.sTl[pslot * 17 + __popc(neg & (bit - 1))] = lane;
        }
        __syncthreads();

        float4 ws4 = ((float4*)sm.t.sWs)[lane];
        float4 wd4 = ((float4*)sm.t.sWd)[lane];
        float4 v4  = ((float4*)sm.t.sV)[lane];

        const float* svRow = sm.t.sSv + pslot * 17;
        const int*   tl    = sm.t.sTl + pslot * 17;

        for (int si = q; si < npos; si += 2) {
            int s = sm.t.sPl[pslot * 17 + si];
            float ssp = svRow[s];
            float4 sr = ((float4*)(sm.t.sSrc + s * D))[lane];
            float4 base;
            base.x = fmaf(ssp, ws4.x, sr.x);
            base.y = fmaf(ssp, ws4.y, sr.y);
            base.z = fmaf(ssp, ws4.z, sr.z);
            base.w = fmaf(ssp, ws4.w, sr.w);
            for (int ti = 0; ti < nneg; ti += 8) {
                float sA[8];
                int tt[8];
                #pragma unroll
                for (int j = 0; j < 8; j++) {
                    int idx = ti + j; if (idx > nneg - 1) idx = nneg - 1;
                    int t = tl[idx];
                    tt[j] = t;
                    float dn = -svRow[t];
                    float4 tg = ((float4*)(sm.t.sTgt + t * D))[lane];
                    float4 h;
                    h.x = fmaxf(base.x + fmaf(dn, wd4.x, tg.x), 0.f);
                    h.y = fmaxf(base.y + fmaf(dn, wd4.y, tg.y), 0.f);
                    h.z = fmaxf(base.z + fmaf(dn, wd4.z, tg.z), 0.f);
                    h.w = fmaxf(base.w + fmaf(dn, wd4.w, tg.w), 0.f);
                    sA[j] = fmaf(h.x, v4.x, fmaf(h.y, v4.y, fmaf(h.z, v4.z, h.w * v4.w)));
                }
                float tot0 = fold4(sA[0], sA[1], sA[2], sA[3]);
                float tot1 = fold4(sA[4], sA[5], sA[6], sA[7]);
                int tm0 = (lane & 16) ? ((lane & 8) ? tt[3] : tt[1])
                                      : ((lane & 8) ? tt[2] : tt[0]);
                int tm1 = (lane & 16) ? ((lane & 8) ? tt[7] : tt[5])
                                      : ((lane & 8) ? tt[6] : tt[4]);
                if (((lane & 7) == 0) && (ti + jm < nneg))
                    sm.t.sRes[(s * 16 + tm0) * 5 + pslot] = tot0;
                if (((lane & 7) == 0) && (ti + 4 + jm < nneg))
                    sm.t.sRes[(s * 16 + tm1) * 5 + pslot] = tot1;
            }
        }
        __syncthreads();

        float b2 = b2t[0];
        for (int i = tid; i < 1024; i += 256) {
            int st = i >> 2, pw = i & 3;
            int s = st >> 4, t = st & 15;
            float svs = sm.t.sSv[pw * 17 + s];
            float svt = sm.t.sSv[pw * 17 + t];
            float val = 0.f;
            if (svs > 0.f && svt < 0.f) {
                float x = sm.t.sRes[st * 5 + pw] + b2;
                val = fminf(svs, -svt) * __fdividef(1.f, 1.f + __expf(-x));
            }
            outT[st * P + pbase + pw] = val;
        }
        return;
    }

    // ================= reorder role: 8 p, warp per p =================
    {
        gate_wait(&g_flagE, 256);
        gate_consume(&g_flagE, &g_consE, 512);

        if (tid < 128) {
            sm.r.sC[tid]       = W1r[tid * 132 + 128];
            sm.r.sC[128 + tid] = W1r[tid * 132 + 129];
            sm.r.sC[256 + tid] = W1r[tid * 132 + 131];
            sm.r.sC[384 + tid] = W2r[tid];
        }
        __syncthreads();

        float4 c0 = ((float4*)sm.r.sC)[lane];
        float4 c1 = ((float4*)(sm.r.sC + 128))[lane];
        float4 c3 = ((float4*)(sm.r.sC + 256))[lane];
        float4 v  = ((float4*)(sm.r.sC + 384))[lane];

        int pbase = (bid - 1288) * 8;
        int p = pbase + w;
        float4 e = ((const float4*)(g_emb + p * D))[lane];

        #pragma unroll 2
        for (int bq = 0; bq < B; bq += 8) {
            float sA[8];
            #pragma unroll
            for (int j = 0; j < 8; j++) {
                int item = (bq + j) * P + p;
                float df = __ldg(&demand[item]);
                float lt = __ldg(&lead[item]);
                float cs = __ldg(&cur_stock[item]);
                float4 h;
                h.x = fmaxf(fmaf(cs, c3.x, fmaf(lt, c1.x, fmaf(df, c0.x, e.x))), 0.f);
                h.y = fmaxf(fmaf(cs, c3.y, fmaf(lt, c1.y, fmaf(df, c0.y, e.y))), 0.f);
                h.z = fmaxf(fmaf(cs, c3.z, fmaf(lt, c1.z, fmaf(df, c0.z, e.z))), 0.f);
                h.w = fmaxf(fmaf(cs, c3.w, fmaf(lt, c1.w, fmaf(df, c0.w, e.w))), 0.f);
                sA[j] = fmaf(h.x, v.x, fmaf(h.y, v.y, fmaf(h.z, v.z, h.w * v.w)));
            }
            float t0 = fold4(sA[0], sA[1], sA[2], sA[3]);
            float t1 = fold4(sA[4], sA[5], sA[6], sA[7]);
            if ((lane & 7) == 0) {
                sm.r.sX[w][bq + jm]     = t0;
                sm.r.sX[w][bq + 4 + jm] = t1;
            }
        }
        __syncthreads();

        float bb = b2r[0];
        for (int i = tid; i < 512; i += 256) {
            int b = i >> 3, pw = i & 7;
            float x = sm.r.sX[pw][b] + bb;
            outR[b * P + pbase + pw] = fmaxf(x, 0.f) + log1pf(__expf(-fabsf(x)));
        }
    }
}

// ---------------------------------------------------------------------------
extern "C" void kernel_launch(void* const* d_in, const int* in_sizes, int n_in,
                              void* d_out, int out_size) {
    const float* current_stock     = (const float*)d_in[0];
    const float* demand_forecast   = (const float*)d_in[1];
    const float* lead_times        = (const float*)d_in[2];
    const float* warehouse_stocks  = (const float*)d_in[3];
    const float* warehouse_demands = (const float*)d_in[4];
    const float* part_emb          = (const float*)d_in[5];
    const float* wh_emb            = (const float*)d_in[6];
    const float* W1r               = (const float*)d_in[7];
    const float* b1r               = (const float*)d_in[8];
    const float* W2r               = (const float*)d_in[9];
    const float* b2r               = (const float*)d_in[10];
    const float* W1t               = (const float*)d_in[11];
    const float* b1t               = (const float*)d_in[12];
    const float* W2t               = (const float*)d_in[13];
    const float* b2t               = (const float*)d_in[14];

    float* out_reorder  = (float*)d_out;              // [B, P]
    float* out_transfer = (float*)d_out + B * P;      // [W, W, P]

    k_all<<<1800, 256>>>(current_stock, demand_forecast, lead_times,
                         warehouse_stocks, warehouse_demands,
                         part_emb, wh_emb,
                         W1r, b1r, W2r, b2r,
                         W1t, b1t, W2t, b2t,
                         out_reorder, out_transfer);
}

// round 12
// speedup vs baseline: 1.2908x; 1.0748x over previous
#include <cuda_runtime.h>
#include <math.h>

#define FULL 0xFFFFFFFFu

constexpr int B  = 64;
constexpr int P  = 4096;
constexpr int W  = 16;
constexpr int D  = 128;
constexpr int Dw = 64;

// W1r: (D, D+4) row-major, stride 132.  W1t: (D, 2*Dw+2) row-major, stride 130.

__device__ float g_src[W * D];
__device__ float g_tgt[W * D];
__device__ float g_emb[P * D];

// 4-way batched warp reduction (6 shuffles for 4 sums).
// lane group j = ((lane>>4)&1) | ((lane>>2)&2) holds total of s_j.
__device__ __forceinline__ float fold4(float s0, float s1, float s2, float s3) {
    bool hi16 = (threadIdx.x & 16) != 0;
    bool hi8  = (threadIdx.x & 8) != 0;
    float a   = hi16 ? s0 : s1;
    float v01 = (hi16 ? s1 : s0) + __shfl_xor_sync(FULL, a, 16);
    float b   = hi16 ? s2 : s3;
    float v23 = (hi16 ? s3 : s2) + __shfl_xor_sync(FULL, b, 16);
    float c   = hi8 ? v01 : v23;
    float vv  = (hi8 ? v23 : v01) + __shfl_xor_sync(FULL, c, 8);
    vv += __shfl_xor_sync(FULL, vv, 4);
    vv += __shfl_xor_sync(FULL, vv, 2);
    vv += __shfl_xor_sync(FULL, vv, 1);
    return vv;
}

// ---------------------------------------------------------------------------
// k_srctgt: 8 blocks x 256 — src/tgt pair-term mini-GEMMs
// ---------------------------------------------------------------------------
__global__ void k_srctgt(const float* __restrict__ wh_emb,
                         const float* __restrict__ W1t,
                         const float* __restrict__ b1t) {
    int bid = blockIdx.x, tid = threadIdx.x;
    #pragma unroll
    for (int r = 0; r < 2; r++) {
        int idx = bid * 512 + r * 256 + tid;   // 0..4095
        int arr = idx >> 11;
        int rem = idx & 2047;
        int s = rem >> 7, d = rem & 127;
        const float* wrow = wh_emb + s * Dw;
        const float* wcol = W1t + d * 130 + arr * Dw;
        float acc = (arr == 0) ? b1t[d] : 0.f;
        #pragma unroll 8
        for (int k = 0; k < Dw; k++) acc = fmaf(wrow[k], wcol[k], acc);
        if (arr == 0) g_src[s * D + d] = acc;
        else          g_tgt[s * D + d] = acc;
    }
}

// ---------------------------------------------------------------------------
// k_emb: 128 blocks x 256, 68KB dyn smem — R7's emb verbatim (32 p / block)
// ---------------------------------------------------------------------------
__global__ void k_emb(const float* __restrict__ part_emb,
                      const float* __restrict__ W1r,
                      const float* __restrict__ b1r) {
    extern __shared__ float dsm[];          // sWT[128*132] + sBias[128]
    int bid = blockIdx.x, tid = threadIdx.x;
    float* sWT   = dsm;
    float* sBias = dsm + 128 * 132;
    for (int i = tid; i < 128 * 128; i += 256) {
        int d = i >> 7, k = i & 127;
        sWT[k * 132 + d] = W1r[d * 132 + k];
    }
    if (tid < 128) sBias[tid] = b1r[tid] + 0.95f * W1r[tid * 132 + 130];
    __syncthreads();

    int w = tid >> 5, lane = tid & 31;
    int p0 = bid * 32 + w * 4;
    const float4* e0 = (const float4*)(part_emb + (p0 + 0) * D);
    const float4* e1 = (const float4*)(part_emb + (p0 + 1) * D);
    const float4* e2 = (const float4*)(part_emb + (p0 + 2) * D);
    const float4* e3 = (const float4*)(part_emb + (p0 + 3) * D);
    float4 bias = ((const float4*)sBias)[lane];
    float4 a0 = bias, a1 = bias, a2 = bias, a3 = bias;
    #pragma unroll 4
    for (int k4 = 0; k4 < 32; k4++) {
        const float* wt = sWT + k4 * 4 * 132;
        float4 w0 = ((const float4*)(wt))[lane];
        float4 w1 = ((const float4*)(wt + 132))[lane];
        float4 w2 = ((const float4*)(wt + 264))[lane];
        float4 w3 = ((const float4*)(wt + 396))[lane];
        float4 ea = __ldg(&e0[k4]);
        float4 eb = __ldg(&e1[k4]);
        float4 ec = __ldg(&e2[k4]);
        float4 ed = __ldg(&e3[k4]);
        #define ACC(A, E) \
            A.x = fmaf(E.x, w0.x, fmaf(E.y, w1.x, fmaf(E.z, w2.x, fmaf(E.w, w3.x, A.x)))); \
            A.y = fmaf(E.x, w0.y, fmaf(E.y, w1.y, fmaf(E.z, w2.y, fmaf(E.w, w3.y, A.y)))); \
            A.z = fmaf(E.x, w0.z, fmaf(E.y, w1.z, fmaf(E.z, w2.z, fmaf(E.w, w3.z, A.z)))); \
            A.w = fmaf(E.x, w0.w, fmaf(E.y, w1.w, fmaf(E.z, w2.w, fmaf(E.w, w3.w, A.w))));
        ACC(a0, ea) ACC(a1, eb) ACC(a2, ec) ACC(a3, ed)
        #undef ACC
    }
    ((float4*)(g_emb + (p0 + 0) * D))[lane] = a0;
    ((float4*)(g_emb + (p0 + 1) * D))[lane] = a1;
    ((float4*)(g_emb + (p0 + 2) * D))[lane] = a2;
    ((float4*)(g_emb + (p0 + 3) * D))[lane] = a3;
}

// ---------------------------------------------------------------------------
// k_transfer: 1024 blocks x 256 — R7 transfer role verbatim (4 p / block)
// ---------------------------------------------------------------------------
__global__ void __launch_bounds__(256, 5)
k_transfer(const float* __restrict__ wstk,
           const float* __restrict__ wdem,
           const float* __restrict__ W1t,
           const float* __restrict__ W2t,
           const float* __restrict__ b2t,
           float* __restrict__ outT) {
    __shared__ float sSrc[W * D];
    __shared__ float sTgt[W * D];
    __shared__ float sWs[D], sWd[D], sV[D];
    __shared__ float sRes[256 * 5];
    __shared__ float sSv[4 * 17];
    __shared__ int   sPl[4 * 17];
    __shared__ int   sTl[4 * 17];

    int tid = threadIdx.x;
    int bid = blockIdx.x;
    int w = tid >> 5, lane = tid & 31;
    int jm = ((lane >> 4) & 1) | ((lane >> 2) & 2);

    {
        const float4* gs = (const float4*)g_src;
        const float4* gt = (const float4*)g_tgt;
        float4* ss = (float4*)sSrc;
        float4* st4 = (float4*)sTgt;
        for (int i = tid; i < W * D / 4; i += 256) { ss[i] = gs[i]; st4[i] = gt[i]; }
    }
    if (tid < D) {
        sWs[tid] = W1t[tid * 130 + 128];
        sWd[tid] = W1t[tid * 130 + 129];
        sV[tid]  = W2t[tid];
    }

    int pslot = w >> 1;
    int q = w & 1;
    int pbase = bid * 4;
    int p = pbase + pslot;

    float sv = 0.f;
    if (lane < W) sv = wstk[lane * P + p] - wdem[lane * P + p];
    unsigned pos = __ballot_sync(FULL, (lane < W) && (sv > 0.f));
    unsigned neg = __ballot_sync(FULL, (lane < W) && (sv < 0.f));
    int npos = __popc(pos);
    int nneg = __popc(neg);

    if (q == 0 && lane < W) {
        sSv[pslot * 17 + lane] = sv;
        unsigned bit = 1u << lane;
        if (pos & bit) sPl[pslot * 17 + __popc(pos & (bit - 1))] = lane;
        if (neg & bit) sTl[pslot * 17 + __popc(neg & (bit - 1))] = lane;
    }
    __syncthreads();

    float4 ws4 = ((float4*)sWs)[lane];
    float4 wd4 = ((float4*)sWd)[lane];
    float4 v4  = ((float4*)sV)[lane];

    const float* svRow = sSv + pslot * 17;
    const int*   tl    = sTl + pslot * 17;

    for (int si = q; si < npos; si += 2) {
        int s = sPl[pslot * 17 + si];
        float ssp = svRow[s];
        float4 sr = ((float4*)(sSrc + s * D))[lane];
        float4 base;
        base.x = fmaf(ssp, ws4.x, sr.x);
        base.y = fmaf(ssp, ws4.y, sr.y);
        base.z = fmaf(ssp, ws4.z, sr.z);
        base.w = fmaf(ssp, ws4.w, sr.w);
        for (int ti = 0; ti < nneg; ti += 8) {
            float sA[8];
            int tt[8];
            #pragma unroll
            for (int j = 0; j < 8; j++) {
                int idx = ti + j; if (idx > nneg - 1) idx = nneg - 1;
                int t = tl[idx];
                tt[j] = t;
                float dn = -svRow[t];
                float4 tg = ((float4*)(sTgt + t * D))[lane];
                float4 h;
                h.x = fmaxf(base.x + fmaf(dn, wd4.x, tg.x), 0.f);
                h.y = fmaxf(base.y + fmaf(dn, wd4.y, tg.y), 0.f);
                h.z = fmaxf(base.z + fmaf(dn, wd4.z, tg.z), 0.f);
                h.w = fmaxf(base.w + fmaf(dn, wd4.w, tg.w), 0.f);
                sA[j] = fmaf(h.x, v4.x, fmaf(h.y, v4.y, fmaf(h.z, v4.z, h.w * v4.w)));
            }
            float tot0 = fold4(sA[0], sA[1], sA[2], sA[3]);
            float tot1 = fold4(sA[4], sA[5], sA[6], sA[7]);
            int tm0 = (lane & 16) ? ((lane & 8) ? tt[3] : tt[1])
                                  : ((lane & 8) ? tt[2] : tt[0]);
            int tm1 = (lane & 16) ? ((lane & 8) ? tt[7] : tt[5])
                                  : ((lane & 8) ? tt[6] : tt[4]);
            if (((lane & 7) == 0) && (ti + jm < nneg))
                sRes[(s * 16 + tm0) * 5 + pslot] = tot0;
            if (((lane & 7) == 0) && (ti + 4 + jm < nneg))
                sRes[(s * 16 + tm1) * 5 + pslot] = tot1;
        }
    }
    __syncthreads();

    float b2 = b2t[0];
    for (int i = tid; i < 1024; i += 256) {
        int st = i >> 2, pw = i & 3;
        int s = st >> 4, t = st & 15;
        float svs = sSv[pw * 17 + s];
        float svt = sSv[pw * 17 + t];
        float val = 0.f;
        if (svs > 0.f && svt < 0.f) {
            float x = sRes[st * 5 + pw] + b2;
            val = fminf(svs, -svt) * __fdividef(1.f, 1.f + __expf(-x));
        }
        outT[st * P + pbase + pw] = val;
    }
}

// ---------------------------------------------------------------------------
// k_reorder: 512 blocks x 256 — R7 reorder role verbatim (8 p / block)
// ---------------------------------------------------------------------------
__global__ void __launch_bounds__(256, 5)
k_reorder(const float* __restrict__ cur_stock,
          const float* __restrict__ demand,
          const float* __restrict__ lead,
          const float* __restrict__ W1r,
          const float* __restrict__ W2r,
          const float* __restrict__ b2r,
          float* __restrict__ outR) {
    __shared__ float sC[4 * 128];
    __shared__ float sX[8][65];
    int tid = threadIdx.x;
    int w = tid >> 5, lane = tid & 31;
    int jm = ((lane >> 4) & 1) | ((lane >> 2) & 2);

    if (tid < 128) {
        sC[tid]       = W1r[tid * 132 + 128];
        sC[128 + tid] = W1r[tid * 132 + 129];
        sC[256 + tid] = W1r[tid * 132 + 131];
        sC[384 + tid] = W2r[tid];
    }
    __syncthreads();

    float4 c0 = ((float4*)sC)[lane];
    float4 c1 = ((float4*)(sC + 128))[lane];
    float4 c3 = ((float4*)(sC + 256))[lane];
    float4 v  = ((float4*)(sC + 384))[lane];

    int pbase = blockIdx.x * 8;
    int p = pbase + w;
    float4 e = ((const float4*)(g_emb + p * D))[lane];

    #pragma unroll 2
    for (int bq = 0; bq < B; bq += 8) {
        float sA[8];
        #pragma unroll
        for (int j = 0; j < 8; j++) {
            int item = (bq + j) * P + p;
            float df = __ldg(&demand[item]);
            float lt = __ldg(&lead[item]);
            float cs = __ldg(&cur_stock[item]);
            float4 h;
            h.x = fmaxf(fmaf(cs, c3.x, fmaf(lt, c1.x, fmaf(df, c0.x, e.x))), 0.f);
            h.y = fmaxf(fmaf(cs, c3.y, fmaf(lt, c1.y, fmaf(df, c0.y, e.y))), 0.f);
            h.z = fmaxf(fmaf(cs, c3.z, fmaf(lt, c1.z, fmaf(df, c0.z, e.z))), 0.f);
            h.w = fmaxf(fmaf(cs, c3.w, fmaf(lt, c1.w, fmaf(df, c0.w, e.w))), 0.f);
            sA[j] = fmaf(h.x, v.x, fmaf(h.y, v.y, fmaf(h.z, v.z, h.w * v.w)));
        }
        float t0 = fold4(sA[0], sA[1], sA[2], sA[3]);
        float t1 = fold4(sA[4], sA[5], sA[6], sA[7]);
        if ((lane & 7) == 0) {
            sX[w][bq + jm]     = t0;
            sX[w][bq + 4 + jm] = t1;
        }
    }
    __syncthreads();

    float bb = b2r[0];
    for (int i = tid; i < 512; i += 256) {
        int b = i >> 3, pw = i & 7;
        float x = sX[pw][b] + bb;
        outR[b * P + pbase + pw] = fmaxf(x, 0.f) + log1pf(__expf(-fabsf(x)));
    }
}

// ---------------------------------------------------------------------------
extern "C" void kernel_launch(void* const* d_in, const int* in_sizes, int n_in,
                              void* d_out, int out_size) {
    const float* current_stock     = (const float*)d_in[0];
    const float* demand_forecast   = (const float*)d_in[1];
    const float* lead_times        = (const float*)d_in[2];
    const float* warehouse_stocks  = (const float*)d_in[3];
    const float* warehouse_demands = (const float*)d_in[4];
    const float* part_emb          = (const float*)d_in[5];
    const float* wh_emb            = (const float*)d_in[6];
    const float* W1r               = (const float*)d_in[7];
    const float* b1r               = (const float*)d_in[8];
    const float* W2r               = (const float*)d_in[9];
    const float* b2r               = (const float*)d_in[10];
    const float* W1t               = (const float*)d_in[11];
    const float* b1t               = (const float*)d_in[12];
    const float* W2t               = (const float*)d_in[13];
    const float* b2t               = (const float*)d_in[14];

    float* out_reorder  = (float*)d_out;              // [B, P]
    float* out_transfer = (float*)d_out + B * P;      // [W, W, P]

    const int dyn = (128 * 132 + 128) * sizeof(float);   // 68096 B

    static cudaStream_t s1 = nullptr;
    static cudaEvent_t evFork = nullptr, evJoin = nullptr;
    if (!s1) {
        // first call is the uncaptured correctness run — safe to create here
        cudaStreamCreateWithFlags(&s1, cudaStreamNonBlocking);
        cudaEventCreateWithFlags(&evFork, cudaEventDisableTiming);
        cudaEventCreateWithFlags(&evJoin, cudaEventDisableTiming);
        cudaFuncSetAttribute(k_emb, cudaFuncAttributeMaxDynamicSharedMemorySize, dyn);
    }

    // fork: stream1 branch = emb -> reorder (only reorder depends on emb)
    cudaEventRecord(evFork, 0);
    cudaStreamWaitEvent(s1, evFork, 0);

    k_emb<<<128, 256, dyn, s1>>>(part_emb, W1r, b1r);

    k_srctgt<<<8, 256>>>(wh_emb, W1t, b1t);
    k_transfer<<<1024, 256>>>(warehouse_stocks, warehouse_demands,
                              W1t, W2t, b2t, out_transfer);

    k_reorder<<<512, 256, 0, s1>>>(current_stock, demand_forecast, lead_times,
                                   W1r, W2r, b2r, out_reorder);

    // join back to the capture stream
    cudaEventRecord(evJoin, s1);
    cudaStreamWaitEvent(0, evJoin, 0);
}

// round 13
// speedup vs baseline: 1.3487x; 1.0449x over previous
#include <cuda_runtime.h>
#include <math.h>

#define FULL 0xFFFFFFFFu
typedef unsigned long long ull;

constexpr int B  = 64;
constexpr int P  = 4096;
constexpr int W  = 16;
constexpr int D  = 128;
constexpr int Dw = 64;

// W1r: (D, D+4) row-major, stride 132.  W1t: (D, 2*Dw+2) row-major, stride 130.

__device__ float g_src[W * D];
__device__ float g_tgt[W * D];
__device__ float g_emb[P * D];

// ---- f32x2 packed helpers (dual-rate fp32; compiled OK on this harness in R3) ----
__device__ __forceinline__ ull pk2(float a, float b) {
    ull r; asm("mov.b64 %0, {%1, %2};" : "=l"(r) : "f"(a), "f"(b)); return r;
}
__device__ __forceinline__ void upk2(ull d, float& a, float& b) {
    asm("mov.b64 {%0, %1}, %2;" : "=f"(a), "=f"(b) : "l"(d));
}
__device__ __forceinline__ ull fma2(ull a, ull b, ull c) {
    ull d; asm("fma.rn.f32x2 %0, %1, %2, %3;" : "=l"(d) : "l"(a), "l"(b), "l"(c)); return d;
}
__device__ __forceinline__ ull add2(ull a, ull b) {
    ull d; asm("add.rn.f32x2 %0, %1, %2;" : "=l"(d) : "l"(a), "l"(b)); return d;
}

// 4-way batched warp reduction (6 shuffles for 4 sums).
// lane group j = ((lane>>4)&1) | ((lane>>2)&2) holds total of s_j.
__device__ __forceinline__ float fold4(float s0, float s1, float s2, float s3) {
    bool hi16 = (threadIdx.x & 16) != 0;
    bool hi8  = (threadIdx.x & 8) != 0;
    float a   = hi16 ? s0 : s1;
    float v01 = (hi16 ? s1 : s0) + __shfl_xor_sync(FULL, a, 16);
    float b   = hi16 ? s2 : s3;
    float v23 = (hi16 ? s3 : s2) + __shfl_xor_sync(FULL, b, 16);
    float c   = hi8 ? v01 : v23;
    float vv  = (hi8 ? v23 : v01) + __shfl_xor_sync(FULL, c, 8);
    vv += __shfl_xor_sync(FULL, vv, 4);
    vv += __shfl_xor_sync(FULL, vv, 2);
    vv += __shfl_xor_sync(FULL, vv, 1);
    return vv;
}

// ---------------------------------------------------------------------------
// k_srctgt: 8 blocks x 256 — src/tgt pair-term mini-GEMMs
// ---------------------------------------------------------------------------
__global__ void k_srctgt(const float* __restrict__ wh_emb,
                         const float* __restrict__ W1t,
                         const float* __restrict__ b1t) {
    int bid = blockIdx.x, tid = threadIdx.x;
    #pragma unroll
    for (int r = 0; r < 2; r++) {
        int idx = bid * 512 + r * 256 + tid;   // 0..4095
        int arr = idx >> 11;
        int rem = idx & 2047;
        int s = rem >> 7, d = rem & 127;
        const float* wrow = wh_emb + s * Dw;
        const float* wcol = W1t + d * 130 + arr * Dw;
        float acc = (arr == 0) ? b1t[d] : 0.f;
        #pragma unroll 8
        for (int k = 0; k < Dw; k++) acc = fmaf(wrow[k], wcol[k], acc);
        if (arr == 0) g_src[s * D + d] = acc;
        else          g_tgt[s * D + d] = acc;
    }
}

// ---------------------------------------------------------------------------
// k_emb: 128 blocks x 256, 68KB dyn smem (32 p / block)
// ---------------------------------------------------------------------------
__global__ void k_emb(const float* __restrict__ part_emb,
                      const float* __restrict__ W1r,
                      const float* __restrict__ b1r) {
    extern __shared__ float dsm[];          // sWT[128*132] + sBias[128]
    int bid = blockIdx.x, tid = threadIdx.x;
    float* sWT   = dsm;
    float* sBias = dsm + 128 * 132;
    for (int i = tid; i < 128 * 128; i += 256) {
        int d = i >> 7, k = i & 127;
        sWT[k * 132 + d] = W1r[d * 132 + k];
    }
    if (tid < 128) sBias[tid] = b1r[tid] + 0.95f * W1r[tid * 132 + 130];
    __syncthreads();

    int w = tid >> 5, lane = tid & 31;
    int p0 = bid * 32 + w * 4;
    const float4* e0 = (const float4*)(part_emb + (p0 + 0) * D);
    const float4* e1 = (const float4*)(part_emb + (p0 + 1) * D);
    const float4* e2 = (const float4*)(part_emb + (p0 + 2) * D);
    const float4* e3 = (const float4*)(part_emb + (p0 + 3) * D);
    float4 bias = ((const float4*)sBias)[lane];
    float4 a0 = bias, a1 = bias, a2 = bias, a3 = bias;
    #pragma unroll 4
    for (int k4 = 0; k4 < 32; k4++) {
        const float* wt = sWT + k4 * 4 * 132;
        float4 w0 = ((const float4*)(wt))[lane];
        float4 w1 = ((const float4*)(wt + 132))[lane];
        float4 w2 = ((const float4*)(wt + 264))[lane];
        float4 w3 = ((const float4*)(wt + 396))[lane];
        float4 ea = __ldg(&e0[k4]);
        float4 eb = __ldg(&e1[k4]);
        float4 ec = __ldg(&e2[k4]);
        float4 ed = __ldg(&e3[k4]);
        #define ACC(A, E) \
            A.x = fmaf(E.x, w0.x, fmaf(E.y, w1.x, fmaf(E.z, w2.x, fmaf(E.w, w3.x, A.x)))); \
            A.y = fmaf(E.x, w0.y, fmaf(E.y, w1.y, fmaf(E.z, w2.y, fmaf(E.w, w3.y, A.y)))); \
            A.z = fmaf(E.x, w0.z, fmaf(E.y, w1.z, fmaf(E.z, w2.z, fmaf(E.w, w3.z, A.z)))); \
            A.w = fmaf(E.x, w0.w, fmaf(E.y, w1.w, fmaf(E.z, w2.w, fmaf(E.w, w3.w, A.w))));
        ACC(a0, ea) ACC(a1, eb) ACC(a2, ec) ACC(a3, ed)
        #undef ACC
    }
    ((float4*)(g_emb + (p0 + 0) * D))[lane] = a0;
    ((float4*)(g_emb + (p0 + 1) * D))[lane] = a1;
    ((float4*)(g_emb + (p0 + 2) * D))[lane] = a2;
    ((float4*)(g_emb + (p0 + 3) * D))[lane] = a3;
}

// ---------------------------------------------------------------------------
// k_transfer: 1024 blocks x 256 (4 p / block), packed f32x2 inner loop
// ---------------------------------------------------------------------------
__global__ void __launch_bounds__(256, 5)
k_transfer(const float* __restrict__ wstk,
           const float* __restrict__ wdem,
           const float* __restrict__ W1t,
           const float* __restrict__ W2t,
           const float* __restrict__ b2t,
           float* __restrict__ outT) {
    __shared__ float sSrc[W * D];
    __shared__ float sTgt[W * D];
    __shared__ float sWs[D], sWd[D], sV[D];
    __shared__ float sRes[256 * 5];
    __shared__ float sSv[4 * 17];
    __shared__ int   sPl[4 * 17];
    __shared__ int   sTl[4 * 17];

    int tid = threadIdx.x;
    int bid = blockIdx.x;
    int w = tid >> 5, lane = tid & 31;
    int jm = ((lane >> 4) & 1) | ((lane >> 2) & 2);

    {
        const float4* gs = (const float4*)g_src;
        const float4* gt = (const float4*)g_tgt;
        float4* ss = (float4*)sSrc;
        float4* st4 = (float4*)sTgt;
        for (int i = tid; i < W * D / 4; i += 256) { ss[i] = gs[i]; st4[i] = gt[i]; }
    }
    if (tid < D) {
        sWs[tid] = W1t[tid * 130 + 128];
        sWd[tid] = W1t[tid * 130 + 129];
        sV[tid]  = W2t[tid];
    }

    int pslot = w >> 1;
    int q = w & 1;
    int pbase = bid * 4;
    int p = pbase + pslot;

    float sv = 0.f;
    if (lane < W) sv = wstk[lane * P + p] - wdem[lane * P + p];
    unsigned pos = __ballot_sync(FULL, (lane < W) && (sv > 0.f));
    unsigned neg = __ballot_sync(FULL, (lane < W) && (sv < 0.f));
    int npos = __popc(pos);
    int nneg = __popc(neg);

    if (q == 0 && lane < W) {
        sSv[pslot * 17 + lane] = sv;
        unsigned bit = 1u << lane;
        if (pos & bit) sPl[pslot * 17 + __popc(pos & (bit - 1))] = lane;
        if (neg & bit) sTl[pslot * 17 + __popc(neg & (bit - 1))] = lane;
    }
    __syncthreads();

    ulonglong2 ws2 = ((const ulonglong2*)sWs)[lane];   // ws01, ws23
    ulonglong2 wd2 = ((const ulonglong2*)sWd)[lane];
    ulonglong2 v2  = ((const ulonglong2*)sV)[lane];
    ull z2 = 0;

    const float* svRow = sSv + pslot * 17;
    const int*   tl    = sTl + pslot * 17;

    for (int si = q; si < npos; si += 2) {
        int s = sPl[pslot * 17 + si];
        float ssp = svRow[s];
        ull ssp2 = pk2(ssp, ssp);
        ulonglong2 sr2 = ((const ulonglong2*)(sSrc + s * D))[lane];
        ull b01 = fma2(ssp2, ws2.x, sr2.x);
        ull b23 = fma2(ssp2, ws2.y, sr2.y);
        for (int ti = 0; ti < nneg; ti += 8) {
            float sA[8];
            int tt[8];
            #pragma unroll
            for (int j = 0; j < 8; j++) {
                int idx = ti + j; if (idx > nneg - 1) idx = nneg - 1;
                int t = tl[idx];
                tt[j] = t;
                float dn = -svRow[t];
                ull dn2 = pk2(dn, dn);
                ulonglong2 tg2 = ((const ulonglong2*)(sTgt + t * D))[lane];
                ull u0 = add2(b01, fma2(dn2, wd2.x, tg2.x));
                ull u1 = add2(b23, fma2(dn2, wd2.y, tg2.y));
                float h0, h1, h2, h3;
                upk2(u0, h0, h1); upk2(u1, h2, h3);
                ull h01 = pk2(fmaxf(h0, 0.f), fmaxf(h1, 0.f));
                ull h23 = pk2(fmaxf(h2, 0.f), fmaxf(h3, 0.f));
                ull dd = fma2(h01, v2.x, fma2(h23, v2.y, z2));
                float lo, hi; upk2(dd, lo, hi);
                sA[j] = lo + hi;
            }
            float tot0 = fold4(sA[0], sA[1], sA[2], sA[3]);
            float tot1 = fold4(sA[4], sA[5], sA[6], sA[7]);
            int tm0 = (lane & 16) ? ((lane & 8) ? tt[3] : tt[1])
                                  : ((lane & 8) ? tt[2] : tt[0]);
            int tm1 = (lane & 16) ? ((lane & 8) ? tt[7] : tt[5])
                                  : ((lane & 8) ? tt[6] : tt[4]);
            if (((lane & 7) == 0) && (ti + jm < nneg))
                sRes[(s * 16 + tm0) * 5 + pslot] = tot0;
            if (((lane & 7) == 0) && (ti + 4 + jm < nneg))
                sRes[(s * 16 + tm1) * 5 + pslot] = tot1;
        }
    }
    __syncthreads();

    float b2 = b2t[0];
    for (int i = tid; i < 1024; i += 256) {
        int st = i >> 2, pw = i & 3;
        int s = st >> 4, t = st & 15;
        float svs = sSv[pw * 17 + s];
        float svt = sSv[pw * 17 + t];
        float val = 0.f;
        if (svs > 0.f && svt < 0.f) {
            float x = sRes[st * 5 + pw] + b2;
            val = fminf(svs, -svt) * __fdividef(1.f, 1.f + __expf(-x));
        }
        outT[st * P + pbase + pw] = val;
    }
}

// ---------------------------------------------------------------------------
// k_reorder: 1024 blocks x 256 (4 p / block, 2 warps per p splitting b),
// packed f32x2 inner loop
// ---------------------------------------------------------------------------
__global__ void __launch_bounds__(256, 5)
k_reorder(const float* __restrict__ cur_stock,
          const float* __restrict__ demand,
          const float* __restrict__ lead,
          const float* __restrict__ W1r,
          const float* __restrict__ W2r,
          const float* __restrict__ b2r,
          float* __restrict__ outR) {
    __shared__ float sC[4 * 128];
    __shared__ float sX[4][65];
    int tid = threadIdx.x;
    int w = tid >> 5, lane = tid & 31;
    int jm = ((lane >> 4) & 1) | ((lane >> 2) & 2);

    if (tid < 128) {
        sC[tid]       = W1r[tid * 132 + 128];
        sC[128 + tid] = W1r[tid * 132 + 129];
        sC[256 + tid] = W1r[tid * 132 + 131];
        sC[384 + tid] = W2r[tid];
    }
    __syncthreads();

    ulonglong2 c0 = ((const ulonglong2*)sC)[lane];
    ulonglong2 c1 = ((const ulonglong2*)(sC + 128))[lane];
    ulonglong2 c3 = ((const ulonglong2*)(sC + 256))[lane];
    ulonglong2 v2 = ((const ulonglong2*)(sC + 384))[lane];
    ull z2 = 0;

    int pslot = w >> 1;                 // 0..3
    int bh = (w & 1) * 32;              // b-half this warp owns
    int pbase = blockIdx.x * 4;
    int p = pbase + pslot;
    ulonglong2 e2 = ((const ulonglong2*)(g_emb + p * D))[lane];

    #pragma unroll
    for (int bq = bh; bq < bh + 32; bq += 8) {
        float sA[8];
        #pragma unroll
        for (int j = 0; j < 8; j++) {
            int item = (bq + j) * P + p;
            float df = __ldg(&demand[item]);
            float lt = __ldg(&lead[item]);
            float cs = __ldg(&cur_stock[item]);
            ull df2 = pk2(df, df), lt2 = pk2(lt, lt), cs2 = pk2(cs, cs);
            ull t0 = fma2(cs2, c3.x, fma2(lt2, c1.x, fma2(df2, c0.x, e2.x)));
            ull t1 = fma2(cs2, c3.y, fma2(lt2, c1.y, fma2(df2, c0.y, e2.y)));
            float h0, h1, h2, h3;
            upk2(t0, h0, h1); upk2(t1, h2, h3);
            ull h01 = pk2(fmaxf(h0, 0.f), fmaxf(h1, 0.f));
            ull h23 = pk2(fmaxf(h2, 0.f), fmaxf(h3, 0.f));
            ull dd = fma2(h01, v2.x, fma2(h23, v2.y, z2));
            float lo, hi; upk2(dd, lo, hi);
            sA[j] = lo + hi;
        }
        float t0f = fold4(sA[0], sA[1], sA[2], sA[3]);
        float t1f = fold4(sA[4], sA[5], sA[6], sA[7]);
        if ((lane & 7) == 0) {
            sX[pslot][bq + jm]     = t0f;
            sX[pslot][bq + 4 + jm] = t1f;
        }
    }
    __syncthreads();

    float bb = b2r[0];
    {
        int b = tid >> 2, pw = tid & 3;
        float x = sX[pw][b] + bb;
        outR[b * P + pbase + pw] = fmaxf(x, 0.f) + log1pf(__expf(-fabsf(x)));
    }
}

// ---------------------------------------------------------------------------
extern "C" void kernel_launch(void* const* d_in, const int* in_sizes, int n_in,
                              void* d_out, int out_size) {
    const float* current_stock     = (const float*)d_in[0];
    const float* demand_forecast   = (const float*)d_in[1];
    const float* lead_times        = (const float*)d_in[2];
    const float* warehouse_stocks  = (const float*)d_in[3];
    const float* warehouse_demands = (const float*)d_in[4];
    const float* part_emb          = (const float*)d_in[5];
    const float* wh_emb            = (const float*)d_in[6];
    const float* W1r               = (const float*)d_in[7];
    const float* b1r               = (const float*)d_in[8];
    const float* W2r               = (const float*)d_in[9];
    const float* b2r               = (const float*)d_in[10];
    const float* W1t               = (const float*)d_in[11];
    const float* b1t               = (const float*)d_in[12];
    const float* W2t               = (const float*)d_in[13];
    const float* b2t               = (const float*)d_in[14];

    float* out_reorder  = (float*)d_out;              // [B, P]
    float* out_transfer = (float*)d_out + B * P;      // [W, W, P]

    const int dyn = (128 * 132 + 128) * sizeof(float);   // 68096 B

    static cudaStream_t s1 = nullptr;
    static cudaEvent_t evFork = nullptr, evJoin = nullptr;
    if (!s1) {
        // first call is the uncaptured correctness run — safe to create here
        cudaStreamCreateWithFlags(&s1, cudaStreamNonBlocking);
        cudaEventCreateWithFlags(&evFork, cudaEventDisableTiming);
        cudaEventCreateWithFlags(&evJoin, cudaEventDisableTiming);
        cudaFuncSetAttribute(k_emb, cudaFuncAttributeMaxDynamicSharedMemorySize, dyn);
    }

    // fork: stream1 branch = emb -> reorder (only reorder depends on emb)
    cudaEventRecord(evFork, 0);
    cudaStreamWaitEvent(s1, evFork, 0);

    k_emb<<<128, 256, dyn, s1>>>(part_emb, W1r, b1r);

    k_srctgt<<<8, 256>>>(wh_emb, W1t, b1t);
    k_transfer<<<1024, 256>>>(warehouse_stocks, warehouse_demands,
                              W1t, W2t, b2t, out_transfer);

    k_reorder<<<1024, 256, 0, s1>>>(current_stock, demand_forecast, lead_times,
                                    W1r, W2r, b2r, out_reorder);

    // join back to the capture stream
    cudaEventRecord(evJoin, s1);
    cudaStreamWaitEvent(0, evJoin, 0);
}